// round 16
// baseline (speedup 1.0000x reference)
#include <cuda_runtime.h>
#include <cuda_fp16.h>
#include <cstdint>

#define Bv 4
#define Sv 2048
#define Hv 768
#define NHv 12
#define DHv 64
#define WHv 128

typedef __half f16;
typedef unsigned int u32;

// ---------------- scratch (static device globals) ---------------------------
__device__ f16 g_hsh[(size_t)Bv*Sv*Hv];
__device__ f16 g_Wth[(size_t)4*Hv*Hv];      // W^T, rows: [q|k|v|o]
__device__ f16 g_Qh[(size_t)Bv*NHv*Sv*DHv];
__device__ f16 g_Kh[(size_t)Bv*NHv*Sv*DHv];
__device__ f16 g_Vth[(size_t)Bv*NHv*DHv*Sv];   // [z][dh][s]
__device__ f16 g_Eh[(size_t)Bv*NHv*Sv*Sv];     // unnormalized exp, fp16 scratch
__device__ f16 g_ctxh[(size_t)Bv*Sv*Hv];
__device__ float g_preln[(size_t)Bv*Sv*Hv];
__device__ float g_gates[Bv*NHv*Sv];

// ---------------- asm helpers ------------------------------------------------
__device__ __forceinline__ void mma16816(float& c0, float& c1, float& c2, float& c3,
                                         const u32 a[4], const u32 b[2]){
    asm volatile("mma.sync.aligned.m16n8k16.row.col.f32.f16.f16.f32 "
        "{%0,%1,%2,%3}, {%4,%5,%6,%7}, {%8,%9}, {%0,%1,%2,%3};"
        : "+f"(c0), "+f"(c1), "+f"(c2), "+f"(c3)
        : "r"(a[0]), "r"(a[1]), "r"(a[2]), "r"(a[3]), "r"(b[0]), "r"(b[1]));
}
__device__ __forceinline__ void cpa16(void* s, const void* g){
    asm volatile("cp.async.ca.shared.global [%0], [%1], 16;\n"
        :: "r"((u32)__cvta_generic_to_shared(s)), "l"(g));
}
__device__ __forceinline__ void ldm_x4(u32& r0,u32& r1,u32& r2,u32& r3, const void* p){
    asm volatile("ldmatrix.sync.aligned.m8n8.x4.shared.b16 {%0,%1,%2,%3}, [%4];"
        : "=r"(r0),"=r"(r1),"=r"(r2),"=r"(r3)
        : "r"((u32)__cvta_generic_to_shared(p)));
}
#define CP_COMMIT() asm volatile("cp.async.commit_group;\n")
#define CP_WAIT0()  asm volatile("cp.async.wait_group 0;\n")
#define CP_WAIT1()  asm volatile("cp.async.wait_group 1;\n")

// ---------------- prep kernels -----------------------------------------------
__global__ __launch_bounds__(256) void cvt_kernel(const float* __restrict__ x,
    f16* __restrict__ h, int n4)
{
    int i = blockIdx.x*256 + threadIdx.x;
    if (i >= n4) return;
    float4 v = ((const float4*)x)[i];
    ((__half2*)h)[i*2  ] = __floats2half2_rn(v.x, v.y);
    ((__half2*)h)[i*2+1] = __floats2half2_rn(v.z, v.w);
}

__global__ __launch_bounds__(256) void wsplit_kernel(
    const float* __restrict__ w0, const float* __restrict__ w1,
    const float* __restrict__ w2, const float* __restrict__ w3)
{
    __shared__ float t[32][33];
    const float* W = blockIdx.z==0 ? w0 : blockIdx.z==1 ? w1 : blockIdx.z==2 ? w2 : w3;
    f16* oh = g_Wth + (size_t)blockIdx.z*Hv*Hv;
    int k0 = blockIdx.y*32, n0 = blockIdx.x*32;
    int tx = threadIdx.x & 31, ty = threadIdx.x >> 5;   // (32,8)
    #pragma unroll
    for (int r=0;r<32;r+=8) t[ty+r][tx] = W[(size_t)(k0+ty+r)*Hv + n0+tx];
    __syncthreads();
    #pragma unroll
    for (int r=0;r<32;r+=8){
        float v = t[tx][ty+r];                 // = W[k0+tx][n0+ty+r]
        oh[(size_t)(n0+ty+r)*Hv + k0+tx] = __float2half_rn(v);
    }
}

// ---------------- 1-term fp16 GEMM, 3-stage cp.async (QKV / Wo) --------------
// MODE 4: Wo proj -> preln fp32, +bias +resid
// MODE 5: fused QKV (N=3H): Q,K -> fp16 [b,nh,s,dh]; V -> fp16 [b,nh,dh,s]
template<int MODE>
__global__ __launch_bounds__(256,2) void mmagemm(
    const f16* __restrict__ Ah, int lda,
    const f16* __restrict__ Bh, int ldb,
    const float* __restrict__ bias0, const float* __restrict__ bias1,
    const float* __restrict__ bias2,
    const float* __restrict__ e1,   // resid (M4)
    f16* __restrict__ O0, f16* __restrict__ O1, f16* __restrict__ O2,
    float* __restrict__ Of,
    int K)
{
    constexpr int LDSK = 40;
    constexpr int BUF  = 128*LDSK;
    extern __shared__ f16 smem[];
    f16* sAh = smem;                 // 3 stages
    f16* sBh = sAh + 3*BUF;          // 3 stages

    const int tid  = threadIdx.x, lane = tid & 31, warp = tid >> 5;
    const int grp  = lane >> 2,   tig  = lane & 3;
    const int row0 = blockIdx.y*128, col0 = blockIdx.x*128;
    const int warpM = (warp>>2)*64, warpN = (warp&3)*32;
    const int lr = tid>>2, lcc = (tid&3)*8;
    const int aRow  = lane & 15,        aCol8 = (lane >> 4) * 8;
    const int bRow  = (lane & 7) + ((lane >> 4) << 3);
    const int bCol8 = ((lane >> 3) & 1) * 8;

    float c[4][4][4];
    #pragma unroll
    for (int i=0;i<4;i++)
        #pragma unroll
        for (int j=0;j<4;j++)
            #pragma unroll
            for (int r=0;r<4;r++) c[i][j][r]=0.f;

    auto load_tile = [&](int kt, int st){
        const int k0 = kt*32;
        f16* dAh = sAh + st*BUF; f16* dBh = sBh + st*BUF;
        #pragma unroll
        for (int t=0;t<2;t++){
            int r = lr + t*64;
            cpa16(&dAh[r*LDSK+lcc], &Ah[(size_t)(row0+r)*lda + k0+lcc]);
            cpa16(&dBh[r*LDSK+lcc], &Bh[(size_t)(col0+r)*ldb + k0+lcc]);
        }
    };

    const int KT = K/32;
    load_tile(0, 0); CP_COMMIT();
    if (KT > 1){ load_tile(1, 1); CP_COMMIT(); }

    for (int kt=0; kt<KT; kt++){
        if (kt+1 < KT) CP_WAIT1(); else CP_WAIT0();
        __syncthreads();
        if (kt+2 < KT){ load_tile(kt+2, (kt+2)%3); CP_COMMIT(); }
        const int st = kt % 3;
        const f16* pAh = sAh + st*BUF;
        const f16* pBh = sBh + st*BUF;
        #pragma unroll
        for (int ks=0;ks<32;ks+=16){
            u32 a[4][4], b_h[4][2];
            #pragma unroll
            for (int jj=0; jj<4; jj+=2)
                ldm_x4(b_h[jj][0], b_h[jj][1], b_h[jj+1][0], b_h[jj+1][1],
                       &pBh[(warpN + jj*8 + bRow)*LDSK + ks + bCol8]);
            #pragma unroll
            for (int i=0;i<4;i++)
                ldm_x4(a[i][0],a[i][1],a[i][2],a[i][3],
                       &pAh[(warpM + i*16 + aRow)*LDSK + ks + aCol8]);
            #pragma unroll
            for (int i=0;i<4;i++)
                #pragma unroll
                for (int j=0;j<4;j++)
                    mma16816(c[i][j][0],c[i][j][1],c[i][j][2],c[i][j][3], a[i], b_h[j]);
        }
    }

    if (MODE==5){
        const int w = col0/Hv;                 // 0=Q 1=K 2=V
        const float* bias = w==0?bias0 : w==1?bias1 : bias2;
        #pragma unroll
        for (int i=0;i<4;i++){
            #pragma unroll
            for (int j=0;j<4;j++){
                int cn  = col0 + warpN + j*8 + tig*2;
                int cl  = cn - w*Hv;
                int nh  = cl>>6, dh = cl&63;
                #pragma unroll
                for (int half=0; half<2; half++){
                    int r = row0 + warpM + i*16 + grp + half*8;
                    float x0 = c[i][j][half*2  ] + bias[cl  ];
                    float x1 = c[i][j][half*2+1] + bias[cl+1];
                    int b=r>>11, s=r&2047;
                    if (w<2){
                        size_t idx = (((size_t)(b*NHv+nh)*Sv+s)<<6)+dh;
                        f16* PO = w==0 ? O0 : O1;
                        *(__half2*)(PO+idx) = __floats2half2_rn(x0,x1);
                    } else {
                        size_t i0 = ((size_t)(b*NHv+nh)*DHv+dh)*Sv + s;
                        O2[i0]    = __float2half_rn(x0);
                        O2[i0+Sv] = __float2half_rn(x1);
                    }
                }
            }
        }
    } else {   // MODE 4: Of = preln, e1 = residual (hs)
        #pragma unroll
        for (int i=0;i<4;i++){
            #pragma unroll
            for (int j=0;j<4;j++){
                int cn = col0 + warpN + j*8 + tig*2;
                #pragma unroll
                for (int half=0; half<2; half++){
                    int r = row0 + warpM + i*16 + grp + half*8;
                    size_t idx = (size_t)r*Hv + cn;
                    float2 o;
                    o.x = c[i][j][half*2  ] + bias0[cn  ] + e1[idx  ];
                    o.y = c[i][j][half*2+1] + bias0[cn+1] + e1[idx+1];
                    *(float2*)(Of+idx) = o;
                }
            }
        }
    }
}

// ---------------- fused attention: scores + softmax + PV + probs -------------
// Per CTA: q-tile of 128 rows for head z. Loop over 32 k-tiles of 64:
//   S = Q@K^T (regs) -> gate/mask/exp -> E (regs, fp16) -> store E scratch
//   ctx += E @ V  (A-fragments taken directly from S accumulator registers)
// Epilogue: rowL from register sums (2 shuffles), ctx = acc/L -> ctxh,
// then probs pass: re-read own E block (L2-warm), scale by 1/L, write fp32.
__global__ __launch_bounds__(256,2) void fused_attn(
    const f16* __restrict__ Qg, const f16* __restrict__ Kg, const f16* __restrict__ Vg,
    const float* __restrict__ gates, const float* __restrict__ am,
    f16* __restrict__ Escr, float* __restrict__ probs, f16* __restrict__ ctxh)
{
    constexpr int LD = 72;                     // 64 + 8 pad (144B rows)
    extern __shared__ char sm[];
    f16*  sQ   = (f16*)sm;                                  // 128*72*2 = 18432
    f16*  sK   = (f16*)(sm + 18432);                        // 3 * 64*72*2 = 27648
    f16*  sV   = (f16*)(sm + 18432 + 27648);                // 27648
    float* sMB = (float*)(sm + 18432 + 55296);              // 2048*4 = 8192
    float* sInv= (float*)(sm + 18432 + 55296 + 8192);       // 512

    const int tid = threadIdx.x, lane = tid & 31, warp = tid >> 5;
    const int grp = lane >> 2, tig = lane & 3;
    const int z = blockIdx.y, q0 = blockIdx.x*128;
    const int b = z/NHv, nh = z%NHv;
    const int warpM = warp*16;                 // 16-row band per warp
    const int aRow  = lane & 15,        aCol8 = (lane >> 4) * 8;
    const int bRow  = (lane & 7) + ((lane >> 4) << 3);
    const int bCol8 = ((lane >> 3) & 1) * 8;

    const f16* Qz = Qg + (size_t)z*Sv*DHv;
    const f16* Kz = Kg + (size_t)z*Sv*DHv;
    const f16* Vz = Vg + (size_t)z*DHv*Sv;
    f16* Ez = Escr + (size_t)z*Sv*Sv;

    // mask-bias row into smem
    const float* amz = am + (size_t)b*Sv;
    for (int i=tid; i<Sv; i+=256) sMB[i] = (1.f - amz[i])*-10000.f;

    // gate per row (this thread's two rows)
    const float g0 = gates[(size_t)z*Sv + q0 + warpM + grp    ]*0.125f;
    const float g1 = gates[(size_t)z*Sv + q0 + warpM + grp + 8]*0.125f;

    auto loadKV = [&](int kt, int st){
        const int k0 = kt*64;
        int r = tid>>2, cb = (tid&3)*16;
        f16* dK = sK + st*64*LD; f16* dV = sV + st*64*LD;
        cpa16(&dK[r*LD+cb  ], &Kz[(size_t)(k0+r)*DHv + cb  ]);
        cpa16(&dK[r*LD+cb+8], &Kz[(size_t)(k0+r)*DHv + cb+8]);
        cpa16(&dV[r*LD+cb  ], &Vz[(size_t)r*Sv + k0 + cb  ]);
        cpa16(&dV[r*LD+cb+8], &Vz[(size_t)r*Sv + k0 + cb+8]);
    };

    {   // Q tile once (in first commit group)
        int r = tid>>1, cb = (tid&1)*32;
        #pragma unroll
        for (int cc=0;cc<4;cc++)
            cpa16(&sQ[r*LD + cb + cc*8], &Qz[(size_t)(q0+r)*DHv + cb + cc*8]);
    }
    loadKV(0,0); CP_COMMIT();
    loadKV(1,1); CP_COMMIT();

    float cv[8][4];
    #pragma unroll
    for (int j=0;j<8;j++)
        #pragma unroll
        for (int r=0;r<4;r++) cv[j][r]=0.f;
    float rs0 = 0.f, rs1 = 0.f;

    const int KT = Sv/64;                      // 32
    for (int kt=0; kt<KT; kt++){
        if (kt+1 < KT) CP_WAIT1(); else CP_WAIT0();
        __syncthreads();
        if (kt+2 < KT){ loadKV(kt+2, (kt+2)%3); CP_COMMIT(); }
        const f16* pK = sK + (kt%3)*64*LD;
        const f16* pV = sV + (kt%3)*64*LD;

        // S = Q @ K^T   (16 rows x 64 cols per warp)
        float c[8][4];
        #pragma unroll
        for (int j=0;j<8;j++)
            #pragma unroll
            for (int r=0;r<4;r++) c[j][r]=0.f;
        #pragma unroll
        for (int ks=0; ks<64; ks+=16){
            u32 a[4];
            ldm_x4(a[0],a[1],a[2],a[3], &sQ[(warpM + aRow)*LD + ks + aCol8]);
            #pragma unroll
            for (int jj=0; jj<4; jj++){
                u32 b0,b1,b2,b3;
                ldm_x4(b0,b1,b2,b3, &pK[(jj*16 + bRow)*LD + ks + bCol8]);
                u32 bA[2]={b0,b1}, bB[2]={b2,b3};
                mma16816(c[2*jj  ][0],c[2*jj  ][1],c[2*jj  ][2],c[2*jj  ][3], a, bA);
                mma16816(c[2*jj+1][0],c[2*jj+1][1],c[2*jj+1][2],c[2*jj+1][3], a, bB);
            }
        }

        // gate + mask + exp; pack E fragments; spill E to scratch; row sums
        u32 eh[8][2];
        const int kb = kt*64;
        #pragma unroll
        for (int j=0;j<8;j++){
            int col = kb + j*8 + tig*2;
            float mb0 = sMB[col], mb1 = sMB[col+1];
            float e0 = __expf(c[j][0]*g0 + mb0);
            float e1 = __expf(c[j][1]*g0 + mb1);
            float e2 = __expf(c[j][2]*g1 + mb0);
            float e3 = __expf(c[j][3]*g1 + mb1);
            rs0 += e0 + e1;  rs1 += e2 + e3;
            __half2 h01 = __floats2half2_rn(e0,e1);
            __half2 h23 = __floats2half2_rn(e2,e3);
            eh[j][0] = *(u32*)&h01;  eh[j][1] = *(u32*)&h23;
            *(__half2*)(Ez + (size_t)(q0+warpM+grp  )*Sv + col) = h01;
            *(__half2*)(Ez + (size_t)(q0+warpM+grp+8)*Sv + col) = h23;
        }

        // ctx += E @ V   (A-fragments straight from registers)
        #pragma unroll
        for (int kc=0; kc<4; kc++){
            u32 a2[4] = { eh[2*kc][0], eh[2*kc][1], eh[2*kc+1][0], eh[2*kc+1][1] };
            #pragma unroll
            for (int jj=0; jj<4; jj++){
                u32 b0,b1,b2,b3;
                ldm_x4(b0,b1,b2,b3, &pV[(jj*16 + bRow)*LD + kc*16 + bCol8]);
                u32 bA[2]={b0,b1}, bB[2]={b2,b3};
                mma16816(cv[2*jj  ][0],cv[2*jj  ][1],cv[2*jj  ][2],cv[2*jj  ][3], a2, bA);
                mma16816(cv[2*jj+1][0],cv[2*jj+1][1],cv[2*jj+1][2],cv[2*jj+1][3], a2, bB);
            }
        }
    }

    // row sums -> inv; ctx epilogue
    rs0 += __shfl_xor_sync(0xffffffffu, rs0, 1);
    rs0 += __shfl_xor_sync(0xffffffffu, rs0, 2);
    rs1 += __shfl_xor_sync(0xffffffffu, rs1, 1);
    rs1 += __shfl_xor_sync(0xffffffffu, rs1, 2);
    const float inv0 = 1.f/rs0, inv1 = 1.f/rs1;
    if (tig==0){ sInv[warpM+grp] = inv0; sInv[warpM+grp+8] = inv1; }

    {
        size_t i0 = ((size_t)b*Sv + q0 + warpM + grp    )*Hv + nh*64;
        size_t i1 = ((size_t)b*Sv + q0 + warpM + grp + 8)*Hv + nh*64;
        #pragma unroll
        for (int j=0;j<8;j++){
            int dh = j*8 + tig*2;
            *(__half2*)(ctxh + i0 + dh) = __floats2half2_rn(cv[j][0]*inv0, cv[j][1]*inv0);
            *(__half2*)(ctxh + i1 + dh) = __floats2half2_rn(cv[j][2]*inv1, cv[j][3]*inv1);
        }
    }

    __syncthreads();                           // sInv + all E stores visible

    // probs pass: probs = E * inv (fp32), E re-read from (mostly L2-hot) scratch
    {
        const int row = tid>>1, hb = (tid&1)*1024;
        const float inv = sInv[row];
        const f16* er = Ez + (size_t)(q0+row)*Sv + hb;
        float* pr = probs + (size_t)z*Sv*Sv + (size_t)(q0+row)*Sv + hb;
        #pragma unroll 4
        for (int it=0; it<128; it++){
            uint4 u = *(const uint4*)(er + it*8);
            __half2 h0 = *(__half2*)&u.x, h1 = *(__half2*)&u.y;
            __half2 h2 = *(__half2*)&u.z, h3 = *(__half2*)&u.w;
            float4 o0, o1;
            o0.x = __low2float(h0)*inv; o0.y = __high2float(h0)*inv;
            o0.z = __low2float(h1)*inv; o0.w = __high2float(h1)*inv;
            o1.x = __low2float(h2)*inv; o1.y = __high2float(h2)*inv;
            o1.z = __low2float(h3)*inv; o1.w = __high2float(h3)*inv;
            *(float4*)(pr + it*8    ) = o0;
            *(float4*)(pr + it*8 + 4) = o1;
        }
    }
}

// ---------------- helpers ----------------------------------------------------
__device__ __forceinline__ float blockReduceSum(float v, float* red){
    #pragma unroll
    for (int o=16;o;o>>=1) v += __shfl_xor_sync(0xffffffffu, v, o);
    const int lane = threadIdx.x & 31, wid = threadIdx.x >> 5;
    const int nw = blockDim.x >> 5;
    __syncthreads();
    if (lane==0) red[wid]=v;
    __syncthreads();
    if (threadIdx.x==0){
        float s=0.f;
        for (int i=0;i<nw;i++) s+=red[i];
        red[32]=s;
    }
    __syncthreads();
    return red[32];
}

// ---------------- wormhole gate ----------------------------------------------
__global__ __launch_bounds__(128) void gate_kernel(
    const float* __restrict__ hs, const float* __restrict__ Wg1, const float* __restrict__ bg1,
    const float* __restrict__ glnw, const float* __restrict__ glnb,
    const float* __restrict__ Wg2, const float* __restrict__ bg2,
    float* __restrict__ gates)
{
    const int ROWS=8;
    __shared__ float hs_s[ROWS*Hv];
    __shared__ float g_s[ROWS][WHv+4];
    __shared__ float red[40];
    const int tid = threadIdx.x;
    const size_t rowbase = (size_t)blockIdx.x*ROWS;

    for (int i=tid;i<ROWS*Hv;i+=128) hs_s[i] = hs[rowbase*Hv + i];
    __syncthreads();

    float acc[ROWS];
    #pragma unroll
    for (int r=0;r<ROWS;r++) acc[r]=bg1[tid];
    for (int h=0;h<Hv;h++){
        float wv = Wg1[h*WHv + tid];
        #pragma unroll
        for (int r=0;r<ROWS;r++) acc[r] = fmaf(hs_s[r*Hv+h], wv, acc[r]);
    }
    float lw = glnw[tid], lb = glnb[tid];
    #pragma unroll
    for (int r=0;r<ROWS;r++){
        float mu  = blockReduceSum(acc[r], red) * (1.f/WHv);
        float d   = acc[r]-mu;
        float var = blockReduceSum(d*d, red) * (1.f/WHv);
        float gv  = d*rsqrtf(var+1e-12f)*lw + lb;
        g_s[r][tid] = fmaxf(gv, 0.f);
    }
    __syncthreads();
    if (tid < ROWS*NHv){
        int r = tid/NHv, o = tid%NHv;
        float s = bg2[o];
        for (int c=0;c<WHv;c++) s = fmaf(g_s[r][c], Wg2[c*NHv+o], s);
        float gate = 1.f/(1.f+__expf(-s));
        size_t row = rowbase + r;
        int b = (int)(row/Sv), sq = (int)(row%Sv);
        gates[((size_t)(b*NHv+o))*Sv + sq] = gate;
    }
}

// ---------------- final residual LayerNorm -----------------------------------
__global__ __launch_bounds__(256) void ln_kernel(const float* __restrict__ x,
    const float* __restrict__ w, const float* __restrict__ b, float* __restrict__ out)
{
    __shared__ float xs[Hv];
    __shared__ float red[40];
    const size_t row = blockIdx.x;
    const float* xr = x + row*Hv;
    float partial = 0.f;
    for (int i=threadIdx.x;i<Hv;i+=256){ float v=xr[i]; xs[i]=v; partial+=v; }
    float mu = blockReduceSum(partial, red)*(1.f/Hv);
    float p2=0.f;
    for (int i=threadIdx.x;i<Hv;i+=256){ float d=xs[i]-mu; p2+=d*d; }
    float var = blockReduceSum(p2, red)*(1.f/Hv);
    float rs = rsqrtf(var+1e-12f);
    float* o = out + row*Hv;
    for (int i=threadIdx.x;i<Hv;i+=256) o[i] = (xs[i]-mu)*rs*w[i] + b[i];
}

// ---------------- launcher ----------------------------------------------------
extern "C" void kernel_launch(void* const* d_in, const int* in_sizes, int n_in,
                              void* d_out, int out_size)
{
    const float* hs  =(const float*)d_in[0];
    const float* am  =(const float*)d_in[1];
    const float* Wq  =(const float*)d_in[2];
    const float* bq  =(const float*)d_in[3];
    const float* Wk  =(const float*)d_in[4];
    const float* bk  =(const float*)d_in[5];
    const float* Wv  =(const float*)d_in[6];
    const float* bvb =(const float*)d_in[7];
    const float* Wg1 =(const float*)d_in[8];
    const float* bg1 =(const float*)d_in[9];
    const float* glnw=(const float*)d_in[10];
    const float* glnb=(const float*)d_in[11];
    const float* Wg2 =(const float*)d_in[12];
    const float* bg2 =(const float*)d_in[13];
    const float* Wo  =(const float*)d_in[14];
    const float* bo  =(const float*)d_in[15];
    const float* lnw =(const float*)d_in[16];
    const float* lnb =(const float*)d_in[17];

    float* out   = (float*)d_out;
    float* probs = out + (size_t)Bv*Sv*Hv;   // tuple order: (out, probs)

    f16 *hsh,*Wth,*Qh,*Kh,*Vth,*Eh,*ctxh;
    float *preln,*gates;
    cudaGetSymbolAddress((void**)&hsh,  g_hsh);
    cudaGetSymbolAddress((void**)&Wth,  g_Wth);
    cudaGetSymbolAddress((void**)&Qh,   g_Qh);
    cudaGetSymbolAddress((void**)&Kh,   g_Kh);
    cudaGetSymbolAddress((void**)&Vth,  g_Vth);
    cudaGetSymbolAddress((void**)&Eh,   g_Eh);
    cudaGetSymbolAddress((void**)&ctxh, g_ctxh);
    cudaGetSymbolAddress((void**)&preln,g_preln);
    cudaGetSymbolAddress((void**)&gates,g_gates);

    const int M = Bv*Sv;
    const int SMEM_GEMM  = 3*2*128*40*(int)sizeof(f16);   // 61440 B
    const int SMEM_FUSED = 18432 + 27648 + 27648 + 8192 + 512;   // 82432 B

    cudaFuncSetAttribute(mmagemm<4>, cudaFuncAttributeMaxDynamicSharedMemorySize, SMEM_GEMM);
    cudaFuncSetAttribute(mmagemm<5>, cudaFuncAttributeMaxDynamicSharedMemorySize, SMEM_GEMM);
    cudaFuncSetAttribute(fused_attn, cudaFuncAttributeMaxDynamicSharedMemorySize, SMEM_FUSED);

    // prep: hs -> fp16, weight transpose, gates
    int n4 = M*Hv/4;
    cvt_kernel<<<(n4+255)/256, 256>>>(hs, hsh, n4);
    wsplit_kernel<<<dim3(24,24,4), 256>>>(Wq, Wk, Wv, Wo);
    gate_kernel<<<M/8, 128>>>(hs, Wg1, bg1, glnw, glnb, Wg2, bg2, gates);

    // fused QKV projection (1-term, N = 3H against stacked W^T)
    dim3 gQKV(3*Hv/128, M/128, 1);
    mmagemm<5><<<gQKV,256,SMEM_GEMM>>>(hsh,Hv, Wth,Hv,
        bq, bk, bvb, nullptr, Qh, Kh, Vth, nullptr, Hv);

    // fused attention: scores + softmax + PV + probs in one kernel
    fused_attn<<<dim3(Sv/128, Bv*NHv), 256, SMEM_FUSED>>>(
        Qh, Kh, Vth, gates, am, Eh, probs, ctxh);

    // out projection (1-term) + bias + residual, then LayerNorm
    dim3 gWo(Hv/128, M/128, 1);
    mmagemm<4><<<gWo,256,SMEM_GEMM>>>(ctxh,Hv, Wth+(size_t)3*Hv*Hv,Hv,
        bo, nullptr, nullptr, hs, nullptr, nullptr, nullptr, preln, Hv);
    ln_kernel<<<M,256>>>(preln, lnw, lnb, out);
}